// round 11
// baseline (speedup 1.0000x reference)
#include <cuda_runtime.h>
#include <cuda_fp16.h>
#include <cstdint>

// ---------------- problem constants ----------------
#define NSENT   4000
#define LSEQ    128
#define VEC_DIM 50
#define POS_DIM 5
#define EMB     60
#define HID     230
#define PADC    240
#define NPOS    201
#define NBAG    500
#define NREL    25

#define WSTRH   200            // W smem row stride in halfs (400B = 100 words ≡ 4 mod 32)
#define ESTRH   72             // E smem row stride in halfs (144B = 36 words ≡ 4 mod 32)
#define WBYT    (PADC*WSTRH*2) // 96000 B
#define EBYT    (130*ESTRH*2)  // 18720 B
#define SM_W    0
#define SM_E    WBYT
#define SM_RED  (WBYT+EBYT)    // 114720
#define SMEM_TOTAL (SM_RED + 8*PADC*4)   // 122400 B

// ---------------- device scratch ----------------
__device__ __half g_W[PADC * WSTRH];    // pre-padded W: [240 ch][k=b*64+e], fp16
__device__ float  g_H[NSENT * PADC];    // sentence encodings

// ---------------- mma.sync helper (pattern proven in R5-R8 build kernel) ----------------
__device__ __forceinline__ void mma16816(float& c0, float& c1, float& c2, float& c3,
                                         const unsigned a0, const unsigned a1,
                                         const unsigned a2, const unsigned a3,
                                         const unsigned b0, const unsigned b1) {
    asm volatile(
        "mma.sync.aligned.m16n8k16.row.col.f32.f16.f16.f32 "
        "{%0,%1,%2,%3}, {%4,%5,%6,%7}, {%8,%9}, {%0,%1,%2,%3};"
        : "+f"(c0), "+f"(c1), "+f"(c2), "+f"(c3)
        : "r"(a0), "r"(a1), "r"(a2), "r"(a3), "r"(b0), "r"(b1));
}

// ---------------- kernel 1: prep W (fp16, padded, [n][k] layout, stride 200) ----------------
// k = b*64 + e (b=tap 0..2, e=emb dim 0..63; e>=60 zero); n>=HID zero; k>=192 zero.
__global__ void k_prep_W(const float* __restrict__ conv_w) {
    int i = blockIdx.x * 256 + threadIdx.x;
    if (i >= PADC * WSTRH) return;
    int n = i / WSTRH;
    int k = i - n * WSTRH;
    float v = 0.f;
    if (n < HID && k < 192) {
        int b = k >> 6, e = k & 63;
        if (e < EMB) v = conv_w[(n * EMB + e) * 3 + b];
    }
    g_W[i] = __float2half_rn(v);
}

// ---------------- kernel 2: direct conv via mma.sync + maxpool + relu ----------------
// persistent grid (148), 256 threads = 8 warps; warp = one 16-token M-tile.
__global__ __launch_bounds__(256) void k_conv(const int* __restrict__ X,
                                              const int* __restrict__ P1,
                                              const int* __restrict__ P2,
                                              const float* __restrict__ word_emb,
                                              const float* __restrict__ p1e,
                                              const float* __restrict__ p2e,
                                              const float* __restrict__ conv_b) {
    extern __shared__ __align__(16) unsigned char sm[];
    __half* sW   = (__half*)(sm + SM_W);
    __half* sE   = (__half*)(sm + SM_E);
    float*  sRed = (float*)(sm + SM_RED);

    int tid = threadIdx.x, warp = tid >> 5, lane = tid & 31;
    int g = lane >> 2, t4 = lane & 3;
    int m0 = warp * 16;

    // stage W once per CTA (persistent)
    for (int i = tid; i < WBYT / 16; i += 256)
        ((uint4*)sW)[i] = ((const uint4*)g_W)[i];
    float biasr = (tid < HID) ? conv_b[tid] : 0.f;

    for (int s = blockIdx.x; s < NSENT; s += gridDim.x) {
        __syncthreads();                        // prior iter: frags loaded, sRed consumed

        // ---- stage E: row r holds emb token (r-1); rows 0 and 129 are zero pads ----
        if (tid < 130) {
            int e = tid - 1;
            float f[60];
            if (e >= 0 && e < LSEQ) {
                int tok = X [s * LSEQ + e];
                int pa  = P1[s * LSEQ + e];
                int pb  = P2[s * LSEQ + e];
                const float2* wp = (const float2*)(word_emb + (size_t)tok * VEC_DIM);
                #pragma unroll
                for (int j = 0; j < 25; j++) { float2 v = wp[j]; f[2*j] = v.x; f[2*j+1] = v.y; }
                #pragma unroll
                for (int j = 0; j < POS_DIM; j++) f[50 + j] = p1e[pa * POS_DIM + j];
                #pragma unroll
                for (int j = 0; j < POS_DIM; j++) f[55 + j] = p2e[pb * POS_DIM + j];
            } else {
                #pragma unroll
                for (int j = 0; j < 60; j++) f[j] = 0.f;
            }
            __half2* row = (__half2*)(sE + tid * ESTRH);
            #pragma unroll
            for (int j = 0; j < 30; j++) row[j] = __floats2half2_rn(f[2*j], f[2*j+1]);
            row[30] = __floats2half2_rn(0.f, 0.f);      // cols 60..63 zero
            row[31] = __floats2half2_rn(0.f, 0.f);
        }
        __syncthreads();

        // ---- A fragments: token t=m0+g(+8), tap b -> E row t+b ----
        unsigned uA[12][4];
        #pragma unroll
        for (int ks = 0; ks < 12; ks++) {
            int b = ks >> 2;
            int kb = ((ks & 3) * 16 + 2 * t4) * 2;              // byte offset in row
            const unsigned char* p = (const unsigned char*)sE + (m0 + g + b) * (ESTRH*2) + kb;
            uA[ks][0] = *(const unsigned*)(p);
            uA[ks][1] = *(const unsigned*)(p + 8 * (ESTRH*2));
            uA[ks][2] = *(const unsigned*)(p + 16);
            uA[ks][3] = *(const unsigned*)(p + 8 * (ESTRH*2) + 16);
        }

        // ---- N loop: 30 tiles of 8 channels; dual accumulators over K ----
        for (int nt = 0; nt < 30; nt++) {
            int n0 = nt * 8;
            const unsigned char* bp = (const unsigned char*)sW + (n0 + g) * (WSTRH*2) + t4 * 4;
            float a0=0.f,a1=0.f,a2=0.f,a3=0.f;
            float d0=0.f,d1=0.f,d2=0.f,d3=0.f;
            #pragma unroll
            for (int ks = 0; ks < 12; ks += 2) {
                unsigned x0 = *(const unsigned*)(bp + ks * 32);
                unsigned x1 = *(const unsigned*)(bp + ks * 32 + 16);
                mma16816(a0,a1,a2,a3, uA[ks][0],uA[ks][1],uA[ks][2],uA[ks][3], x0, x1);
                unsigned y0 = *(const unsigned*)(bp + ks * 32 + 32);
                unsigned y1 = *(const unsigned*)(bp + ks * 32 + 48);
                mma16816(d0,d1,d2,d3, uA[ks+1][0],uA[ks+1][1],uA[ks+1][2],uA[ks+1][3], y0, y1);
            }
            // rows: c0/c1 = token m0+g, c2/c3 = token m0+g+8; cols n0+2t4, n0+2t4+1
            float v0 = fmaxf(a0 + d0, a2 + d2);
            float v1 = fmaxf(a1 + d1, a3 + d3);
            #pragma unroll
            for (int o = 4; o <= 16; o <<= 1) {         // reduce over g (lane bits 2..4)
                v0 = fmaxf(v0, __shfl_xor_sync(0xffffffffu, v0, o));
                v1 = fmaxf(v1, __shfl_xor_sync(0xffffffffu, v1, o));
            }
            if (lane < 4) {
                sRed[warp * PADC + n0 + 2 * lane]     = v0;
                sRed[warp * PADC + n0 + 2 * lane + 1] = v1;
            }
        }
        __syncthreads();

        // ---- final: max over 8 M-tiles, bias, relu ----
        if (tid < HID) {
            float m = sRed[tid];
            #pragma unroll
            for (int w = 1; w < 8; w++) m = fmaxf(m, sRed[w * PADC + tid]);
            g_H[s * PADC + tid] = fmaxf(m + biasr, 0.f);
        }
    }
}

// ---------------- kernel 3: per-bag softmax attention + classifier ----------------
__global__ __launch_bounds__(256) void k_bags(const int* __restrict__ scope,
                                              const int* __restrict__ relation,
                                              const float* __restrict__ rel_w,
                                              const float* __restrict__ rel_b,
                                              float* __restrict__ out) {
    int b = blockIdx.x;
    __shared__ float s_q[HID];
    __shared__ float s_logit[8];
    __shared__ float s_alpha[8];
    __shared__ float s_rep[HID];

    int tid = threadIdx.x;
    int w = tid >> 5, lane = tid & 31;
    int s0 = scope[2 * b], s1 = scope[2 * b + 1];
    int sz = s1 - s0;
    if (sz > 8) sz = 8;
    int rq = relation[b];

    for (int c = tid; c < HID; c += 256) s_q[c] = rel_w[rq * HID + c];
    __syncthreads();

    if (w < 8) {
        float acc = 0.f;
        if (w < sz) {
            const float* hp = g_H + (size_t)(s0 + w) * PADC;
            for (int c = lane; c < HID; c += 32) acc = fmaf(hp[c], s_q[c], acc);
        }
        #pragma unroll
        for (int o = 16; o; o >>= 1) acc += __shfl_xor_sync(0xffffffffu, acc, o);
        if (lane == 0) s_logit[w] = (w < sz) ? acc : -1e30f;
    }
    __syncthreads();

    if (tid == 0) {
        float m = -1e30f;
        for (int i = 0; i < sz; i++) m = fmaxf(m, s_logit[i]);
        float d = 0.f;
        for (int i = 0; i < sz; i++) { float e = expf(s_logit[i] - m); s_alpha[i] = e; d += e; }
        float inv = 1.f / d;
        for (int i = 0; i < sz; i++) s_alpha[i] *= inv;
    }
    __syncthreads();

    for (int c = tid; c < HID; c += 256) {
        float acc = 0.f;
        for (int i = 0; i < sz; i++)
            acc = fmaf(s_alpha[i], g_H[(size_t)(s0 + i) * PADC + c], acc);
        s_rep[c] = acc;
    }
    __syncthreads();

    for (int rr = w; rr < NREL; rr += 8) {
        float acc = 0.f;
        for (int c = lane; c < HID; c += 32) acc = fmaf(s_rep[c], rel_w[rr * HID + c], acc);
        #pragma unroll
        for (int o = 16; o; o >>= 1) acc += __shfl_xor_sync(0xffffffffu, acc, o);
        if (lane == 0) out[b * NREL + rr] = acc + rel_b[rr];
    }
}

// ---------------- launch ----------------
extern "C" void kernel_launch(void* const* d_in, const int* in_sizes, int n_in,
                              void* d_out, int out_size) {
    const int*   X        = (const int*)  d_in[0];
    const int*   P1       = (const int*)  d_in[1];
    const int*   P2       = (const int*)  d_in[2];
    // d_in[3] mask, d_in[4] length: unused
    const int*   scope    = (const int*)  d_in[5];
    const int*   relation = (const int*)  d_in[6];
    const float* word_emb = (const float*)d_in[7];
    const float* p1e      = (const float*)d_in[8];
    const float* p2e      = (const float*)d_in[9];
    const float* conv_w   = (const float*)d_in[10];
    const float* conv_b   = (const float*)d_in[11];
    const float* rel_w    = (const float*)d_in[12];
    const float* rel_b    = (const float*)d_in[13];
    float* out = (float*)d_out;

    cudaFuncSetAttribute(k_conv, cudaFuncAttributeMaxDynamicSharedMemorySize, SMEM_TOTAL);

    k_prep_W<<<(PADC * WSTRH + 255) / 256, 256>>>(conv_w);
    k_conv<<<148, 256, SMEM_TOTAL>>>(X, P1, P2, word_emb, p1e, p2e, conv_b);
    k_bags<<<NBAG, 256>>>(scope, relation, rel_w, rel_b, out);
}

// round 12
// speedup vs baseline: 1.7301x; 1.7301x over previous
#include <cuda_runtime.h>
#include <cuda_fp16.h>

// ---------------- problem constants ----------------
#define NSENT   4000
#define LSEQ    128
#define VOCAB   50002
#define VEC_DIM 50
#define POS_DIM 5
#define EMB     60
#define HID     230
#define PADC    240            // HID padded to 240
#define ROWW    (3*PADC)       // 720 entries per table row (3 kernel taps)
#define ROWB    (ROWW*2)       // row stride in bytes (fp16)
#define KPAD    64             // VEC_DIM padded to 64 for mma (4 k-steps of 16)
#define NCOLT   (ROWW/8)       // 90 col-tiles of 8
#define NROWT   ((VOCAB+15)/16)// 3126 row-tiles of 16
#define SDSTR   728            // s_D row stride in halfs (16B-aligned, conflict-free)
#define NPOS    201
#define NPAIR   (NPOS*NPOS)    // 40401
#define NBAG    500
#define NREL    25

// ---------------- device scratch (static; no runtime allocation) ----------------
__device__ __half g_Bt  [ROWW * KPAD];              // B transposed for build GEMM
__device__ __half g_Tw  [(size_t)VOCAB * ROWW];     // word projection table (fp16, ~72 MB)
__device__ __half g_Tp1 [NPOS * ROWW];              // pos1 projection table (fp16, 289 KB)
__device__ __half g_Tp2 [NPOS * ROWW];              // pos2 projection table (fp16, 289 KB)
__device__ __half g_Tp12[(size_t)NPAIR * ROWW];     // pos-PAIR table (fp16, ~58 MB)
__device__ float  g_H   [NSENT * PADC];             // sentence encodings

// ---------------- helpers ----------------
__device__ __forceinline__ uint2 ldu2b(const char* p) {
    return *reinterpret_cast<const uint2*>(p);
}
__device__ __forceinline__ __half2 h2lo(uint2 u) { return *reinterpret_cast<__half2*>(&u.x); }
__device__ __forceinline__ __half2 h2hi(uint2 u) { return *reinterpret_cast<__half2*>(&u.y); }

// ---------------- kernel 1: build fp16 transposed weight matrix g_Bt ----------------
__global__ void k_prep_Bt(const float* __restrict__ conv_w) {
    int i = blockIdx.x * blockDim.x + threadIdx.x;
    if (i >= ROWW * KPAD) return;
    int n = i >> 6;            // 0..719
    int k = i & 63;
    int tap = n / PADC;
    int c = n - tap * PADC;
    float v = (c < HID && k < VEC_DIM) ? conv_w[(c * EMB + k) * 3 + tap] : 0.f;
    g_Bt[i] = __float2half_rn(v);
}

// ---------------- kernel 2: tiny pos tables (K=5, fp16 out) ----------------
__global__ void k_pos_tables(const float* __restrict__ p1e,
                             const float* __restrict__ p2e,
                             const float* __restrict__ conv_w) {
    int p = blockIdx.x;        // 0..200
    int r = threadIdx.x;       // 0..719
    int k = r / PADC;
    int c = r - k * PADC;
    float a1 = 0.f, a2 = 0.f;
    if (c < HID) {
        #pragma unroll
        for (int e = 0; e < POS_DIM; e++) {
            float w1 = conv_w[(c * EMB + VEC_DIM + e) * 3 + k];
            float w2 = conv_w[(c * EMB + VEC_DIM + POS_DIM + e) * 3 + k];
            a1 = fmaf(p1e[p * POS_DIM + e], w1, a1);
            a2 = fmaf(p2e[p * POS_DIM + e], w2, a2);
        }
    }
    g_Tp1[p * ROWW + r] = __float2half_rn(a1);
    g_Tp2[p * ROWW + r] = __float2half_rn(a2);
}

// ---------------- kernel 2b: pos-pair outer-sum table ----------------
// T12[p*201+q] = Tp1[p] + Tp2[q]  (store-bound: ~58 MB coalesced)
__global__ __launch_bounds__(192) void k_pair(void) {
    int pr = blockIdx.x;                      // 0..40400
    int p = pr / NPOS, q = pr - p * NPOS;
    int i = threadIdx.x;
    if (i >= 180) return;                     // 180 uint2 = 720 halfs
    uint2 a = ((const uint2*)(g_Tp1 + p * ROWW))[i];
    uint2 b = ((const uint2*)(g_Tp2 + q * ROWW))[i];
    __half2 lo = __hadd2(h2lo(a), h2lo(b));
    __half2 hi = __hadd2(h2hi(a), h2hi(b));
    uint2 st;
    st.x = *reinterpret_cast<unsigned*>(&lo);
    st.y = *reinterpret_cast<unsigned*>(&hi);
    ((uint2*)(g_Tp12 + (size_t)pr * ROWW))[i] = st;
}

// ---------------- kernel 3: word table build via mma.sync + smem-staged stores ----------------
__global__ __launch_bounds__(256) void k_build_word(const float* __restrict__ word_emb) {
    __shared__ __half s_A[16 * 66];
    __shared__ __half s_D[16 * SDSTR];              // staged output strip (~23 KB)
    int row0 = blockIdx.x * 16;
    int tid  = threadIdx.x;

    for (int i = tid; i < 16 * 64; i += 256) {
        int r = i >> 6, k = i & 63;
        int gr = row0 + r;
        float v = (gr < VOCAB && k < VEC_DIM) ? word_emb[gr * VEC_DIM + k] : 0.f;
        s_A[r * 66 + k] = __float2half_rn(v);
    }
    __syncthreads();

    int warp = tid >> 5, lane = tid & 31;
    int g = lane >> 2, t = lane & 3;

    unsigned uA[4][4];
    #pragma unroll
    for (int ks = 0; ks < 4; ks++) {
        int k0 = ks * 16;
        uA[ks][0] = *reinterpret_cast<unsigned*>(&s_A[ g      * 66 + k0 + 2*t    ]);
        uA[ks][1] = *reinterpret_cast<unsigned*>(&s_A[(g + 8) * 66 + k0 + 2*t    ]);
        uA[ks][2] = *reinterpret_cast<unsigned*>(&s_A[ g      * 66 + k0 + 2*t + 8]);
        uA[ks][3] = *reinterpret_cast<unsigned*>(&s_A[(g + 8) * 66 + k0 + 2*t + 8]);
    }

    for (int ct = warp; ct < NCOLT; ct += 8) {
        int n0 = ct * 8;
        float c0 = 0.f, c1 = 0.f, c2 = 0.f, c3 = 0.f;
        #pragma unroll
        for (int ks = 0; ks < 4; ks++) {
            int k0 = ks * 16;
            const __half* bp = g_Bt + (n0 + g) * KPAD + k0 + 2*t;
            unsigned b0 = *reinterpret_cast<const unsigned*>(bp);
            unsigned b1 = *reinterpret_cast<const unsigned*>(bp + 8);
            asm volatile(
                "mma.sync.aligned.m16n8k16.row.col.f32.f16.f16.f32 "
                "{%0,%1,%2,%3}, {%4,%5,%6,%7}, {%8,%9}, {%0,%1,%2,%3};"
                : "+f"(c0), "+f"(c1), "+f"(c2), "+f"(c3)
                : "r"(uA[ks][0]), "r"(uA[ks][1]), "r"(uA[ks][2]), "r"(uA[ks][3]),
                  "r"(b0), "r"(b1));
        }
        int col = n0 + 2*t;
        *reinterpret_cast<__half2*>(&s_D[ g      * SDSTR + col]) = __floats2half2_rn(c0, c1);
        *reinterpret_cast<__half2*>(&s_D[(g + 8) * SDSTR + col]) = __floats2half2_rn(c2, c3);
    }
    __syncthreads();

    int nrow = VOCAB - row0;  if (nrow > 16) nrow = 16;
    for (int i = tid; i < nrow * 90; i += 256) {
        int r = i / 90, u = i - r * 90;
        uint4 val = *reinterpret_cast<uint4*>(&s_D[r * SDSTR + u * 8]);
        *reinterpret_cast<uint4*>(&g_Tw[(size_t)(row0 + r) * ROWW + u * 8]) = val;
    }
}

// ---------------- kernel 4: main fused conv-via-gather + maxpool + relu ----------------
// R6 structure, but 2 tables (word + pos-pair): 6 loads/token, 1-deep register prefetch.
// block = 128 threads = 2 sentences x 64 lanes; lane tc<60 owns 4 channels.
__global__ __launch_bounds__(128, 9) void k_main(const int* __restrict__ X,
                                                 const int* __restrict__ P1,
                                                 const int* __restrict__ P2,
                                                 const float* __restrict__ conv_b) {
    __shared__ int   s_off[2][2][LSEQ + 1];   // BYTE offsets: [grp][word|pair][token]
    __shared__ float s_b[PADC];
    int tid = threadIdx.x;
    int grp = tid >> 6, tc = tid & 63;
    int sent0 = blockIdx.x * 2;

    for (int i = tid; i < 2 * LSEQ; i += 128) {
        int g = i >> 7, t = i & (LSEQ - 1);
        int s = sent0 + g;
        s_off[g][0][t] = X[s * LSEQ + t] * ROWB;
        s_off[g][1][t] = (P1[s * LSEQ + t] * NPOS + P2[s * LSEQ + t]) * ROWB;
    }
    if (tid < 2) {                            // dummy token for prefetch overrun
        s_off[tid][0][LSEQ] = 0;
        s_off[tid][1][LSEQ] = 0;
    }
    for (int i = tid; i < PADC; i += 128) s_b[i] = (i < HID) ? conv_b[i] : 0.f;
    __syncthreads();

    if (tc >= 60) return;
    int cb = tc * 8;                          // channel byte offset within row

    const int* ow = s_off[grp][0];
    const int* op = s_off[grp][1];
    const char* baseW = (const char*)g_Tw   + cb;
    const char* baseP = (const char*)g_Tp12 + cb;

    __half2 maxA  = __float2half2_rn(-60000.f), maxB = maxA;
    __half2 pendA = __float2half2_rn(-16384.f), pendB = pendA;  // absorbs t=0 max-update
    __half2 prevA = __float2half2_rn(0.f),      prevB = prevA;

    // prologue: load t=0
    const char* rw = baseW + ow[0];
    const char* rp = baseP + op[0];
    uint2 w0 = ldu2b(rw);  uint2 w1 = ldu2b(rw + 2*PADC);  uint2 w2 = ldu2b(rw + 4*PADC);
    uint2 p0 = ldu2b(rp);  uint2 p1 = ldu2b(rp + 2*PADC);  uint2 p2 = ldu2b(rp + 4*PADC);

    #pragma unroll 4
    for (int t = 0; t < LSEQ; t++) {
        // issue ALL loads for t+1 before computing on t
        const char* nw = baseW + ow[t + 1];
        const char* np = baseP + op[t + 1];
        uint2 W0 = ldu2b(nw);  uint2 W1 = ldu2b(nw + 2*PADC);  uint2 W2 = ldu2b(nw + 4*PADC);
        uint2 Q0 = ldu2b(np);  uint2 Q1 = ldu2b(np + 2*PADC);  uint2 Q2 = ldu2b(np + 4*PADC);

        __half2 a2A = __hadd2(h2lo(w2), h2lo(p2));
        __half2 a2B = __hadd2(h2hi(w2), h2hi(p2));
        maxA = __hmax2(maxA, __hadd2(pendA, a2A));      // h[t-1]
        maxB = __hmax2(maxB, __hadd2(pendB, a2B));
        __half2 a1A = __hadd2(h2lo(w1), h2lo(p1));
        __half2 a1B = __hadd2(h2hi(w1), h2hi(p1));
        pendA = __hadd2(prevA, a1A);
        pendB = __hadd2(prevB, a1B);
        prevA = __hadd2(h2lo(w0), h2lo(p0));
        prevB = __hadd2(h2hi(w0), h2hi(p0));

        w0 = W0; w1 = W1; w2 = W2;
        p0 = Q0; p1 = Q1; p2 = Q2;
    }
    maxA = __hmax2(maxA, pendA);              // h[L-1] (a2 of pad token = 0)
    maxB = __hmax2(maxB, pendB);

    float2 mA = __half22float2(maxA);
    float2 mB = __half22float2(maxB);
    int s = sent0 + grp;
    int coff = tc * 4;
    g_H[s * PADC + coff + 0] = fmaxf(mA.x + s_b[coff + 0], 0.f);
    g_H[s * PADC + coff + 1] = fmaxf(mA.y + s_b[coff + 1], 0.f);
    g_H[s * PADC + coff + 2] = fmaxf(mB.x + s_b[coff + 2], 0.f);
    g_H[s * PADC + coff + 3] = fmaxf(mB.y + s_b[coff + 3], 0.f);
}

// ---------------- kernel 5: per-bag softmax attention + classifier ----------------
__global__ __launch_bounds__(256) void k_bags(const int* __restrict__ scope,
                                              const int* __restrict__ relation,
                                              const float* __restrict__ rel_w,
                                              const float* __restrict__ rel_b,
                                              float* __restrict__ out) {
    int b = blockIdx.x;
    __shared__ float s_q[HID];
    __shared__ float s_logit[8];
    __shared__ float s_alpha[8];
    __shared__ float s_rep[HID];

    int tid = threadIdx.x;
    int w = tid >> 5, lane = tid & 31;
    int s0 = scope[2 * b], s1 = scope[2 * b + 1];
    int sz = s1 - s0;
    if (sz > 8) sz = 8;
    int rq = relation[b];

    for (int c = tid; c < HID; c += 256) s_q[c] = rel_w[rq * HID + c];
    __syncthreads();

    if (w < 8) {
        float acc = 0.f;
        if (w < sz) {
            const float* hp = g_H + (size_t)(s0 + w) * PADC;
            for (int c = lane; c < HID; c += 32) acc = fmaf(hp[c], s_q[c], acc);
        }
        #pragma unroll
        for (int o = 16; o; o >>= 1) acc += __shfl_xor_sync(0xffffffffu, acc, o);
        if (lane == 0) s_logit[w] = (w < sz) ? acc : -1e30f;
    }
    __syncthreads();

    if (tid == 0) {
        float m = -1e30f;
        for (int i = 0; i < sz; i++) m = fmaxf(m, s_logit[i]);
        float d = 0.f;
        for (int i = 0; i < sz; i++) { float e = expf(s_logit[i] - m); s_alpha[i] = e; d += e; }
        float inv = 1.f / d;
        for (int i = 0; i < sz; i++) s_alpha[i] *= inv;
    }
    __syncthreads();

    for (int c = tid; c < HID; c += 256) {
        float acc = 0.f;
        for (int i = 0; i < sz; i++)
            acc = fmaf(s_alpha[i], g_H[(size_t)(s0 + i) * PADC + c], acc);
        s_rep[c] = acc;
    }
    __syncthreads();

    for (int rr = w; rr < NREL; rr += 8) {
        float acc = 0.f;
        for (int c = lane; c < HID; c += 32) acc = fmaf(s_rep[c], rel_w[rr * HID + c], acc);
        #pragma unroll
        for (int o = 16; o; o >>= 1) acc += __shfl_xor_sync(0xffffffffu, acc, o);
        if (lane == 0) out[b * NREL + rr] = acc + rel_b[rr];
    }
}

// ---------------- launch ----------------
extern "C" void kernel_launch(void* const* d_in, const int* in_sizes, int n_in,
                              void* d_out, int out_size) {
    const int*   X        = (const int*)  d_in[0];
    const int*   P1       = (const int*)  d_in[1];
    const int*   P2       = (const int*)  d_in[2];
    // d_in[3] mask, d_in[4] length: unused
    const int*   scope    = (const int*)  d_in[5];
    const int*   relation = (const int*)  d_in[6];
    const float* word_emb = (const float*)d_in[7];
    const float* p1e      = (const float*)d_in[8];
    const float* p2e      = (const float*)d_in[9];
    const float* conv_w   = (const float*)d_in[10];
    const float* conv_b   = (const float*)d_in[11];
    const float* rel_w    = (const float*)d_in[12];
    const float* rel_b    = (const float*)d_in[13];
    float* out = (float*)d_out;

    k_prep_Bt<<<(ROWW * KPAD + 255) / 256, 256>>>(conv_w);
    k_pos_tables<<<NPOS, ROWW>>>(p1e, p2e, conv_w);
    k_pair<<<NPAIR, 192>>>();
    k_build_word<<<NROWT, 256>>>(word_emb);
    k_main<<<NSENT / 2, 128>>>(X, P1, P2, conv_b);
    k_bags<<<NBAG, 256>>>(scope, relation, rel_w, rel_b, out);
}

// round 13
// speedup vs baseline: 2.6216x; 1.5152x over previous
#include <cuda_runtime.h>
#include <cuda_fp16.h>

// ---------------- problem constants ----------------
#define NSENT   4000
#define LSEQ    128
#define VOCAB   50002
#define VEC_DIM 50
#define POS_DIM 5
#define EMB     60
#define HID     230
#define PADC    240            // HID padded to 240
#define ROWW    (3*PADC)       // 720 entries per table row (3 kernel taps)
#define ROWB    (ROWW*2)       // row stride in bytes (fp16)
#define NCOLT   (ROWW/8)       // 90 col-tiles of 8
#define NROWT   ((VOCAB+15)/16)// 3126 row-tiles of 16
#define SDSTR   728            // s_D row stride in halfs (16B-aligned, conflict-free)
#define NPOS    201
#define NBAG    500
#define NREL    25

// ---------------- device scratch (static; no runtime allocation) ----------------
__device__ uint2  g_Bf [NCOLT * 4 * 32];            // B in MMA-fragment order (90 KB, L1-resident)
__device__ __half g_Tw [(size_t)VOCAB * ROWW];      // word projection table (fp16, ~72 MB)
__device__ __half g_Tp1[NPOS * ROWW];               // pos1 projection table (fp16, 289 KB)
__device__ __half g_Tp2[NPOS * ROWW];               // pos2 projection table (fp16, 289 KB)
__device__ float  g_H  [NSENT * PADC];              // sentence encodings

// ---------------- helpers ----------------
__device__ __forceinline__ uint2 ldu2b(const char* p) {
    return *reinterpret_cast<const uint2*>(p);
}
__device__ __forceinline__ __half2 h2lo(uint2 u) { return *reinterpret_cast<__half2*>(&u.x); }
__device__ __forceinline__ __half2 h2hi(uint2 u) { return *reinterpret_cast<__half2*>(&u.y); }

// ---------------- kernel 1: W in MMA-fragment order ----------------
// g_Bf[((ct*4)+ks)*32 + lane] packs (b0,b1) for mma.m16n8k16 row.col:
// lane=(g,t): n = ct*8+g (output col = tap*240+ch), b0 = halfs (e0,e0+1), b1 = (e0+8,e0+9),
// e0 = ks*16+2t; value = conv_w[ch][e][tap], zero outside HID/VEC_DIM.
__global__ void k_prep_Bf(const float* __restrict__ conv_w) {
    int i = blockIdx.x * 256 + threadIdx.x;
    if (i >= NCOLT * 4 * 32) return;
    int lane = i & 31;
    int ks = (i >> 5) & 3;
    int ct = i >> 7;
    int g = lane >> 2, t = lane & 3;
    int n = ct * 8 + g;
    int tap = n / PADC, c = n - tap * PADC;
    int e0 = ks * 16 + 2 * t;
    float v0 = 0.f, v1 = 0.f, v2 = 0.f, v3 = 0.f;
    if (c < HID) {
        if (e0     < VEC_DIM) v0 = conv_w[(c * EMB + e0    ) * 3 + tap];
        if (e0 + 1 < VEC_DIM) v1 = conv_w[(c * EMB + e0 + 1) * 3 + tap];
        if (e0 + 8 < VEC_DIM) v2 = conv_w[(c * EMB + e0 + 8) * 3 + tap];
        if (e0 + 9 < VEC_DIM) v3 = conv_w[(c * EMB + e0 + 9) * 3 + tap];
    }
    __half2 x = __floats2half2_rn(v0, v1);
    __half2 y = __floats2half2_rn(v2, v3);
    uint2 st;
    st.x = *reinterpret_cast<unsigned*>(&x);
    st.y = *reinterpret_cast<unsigned*>(&y);
    g_Bf[i] = st;
}

// ---------------- kernel 2: tiny pos tables (K=5, fp16 out) ----------------
__global__ void k_pos_tables(const float* __restrict__ p1e,
                             const float* __restrict__ p2e,
                             const float* __restrict__ conv_w) {
    int p = blockIdx.x;        // 0..200
    int r = threadIdx.x;       // 0..719
    int k = r / PADC;
    int c = r - k * PADC;
    float a1 = 0.f, a2 = 0.f;
    if (c < HID) {
        #pragma unroll
        for (int e = 0; e < POS_DIM; e++) {
            float w1 = conv_w[(c * EMB + VEC_DIM + e) * 3 + k];
            float w2 = conv_w[(c * EMB + VEC_DIM + POS_DIM + e) * 3 + k];
            a1 = fmaf(p1e[p * POS_DIM + e], w1, a1);
            a2 = fmaf(p2e[p * POS_DIM + e], w2, a2);
        }
    }
    g_Tp1[p * ROWW + r] = __float2half_rn(a1);
    g_Tp2[p * ROWW + r] = __float2half_rn(a2);
}

// ---------------- kernel 3: word table build via mma.sync + frag-order B + staged stores ----------------
__global__ __launch_bounds__(256) void k_build_word(const float* __restrict__ word_emb) {
    __shared__ __half s_A[16 * 66];
    __shared__ __half s_D[16 * SDSTR];              // staged output strip (~23 KB)
    int row0 = blockIdx.x * 16;
    int tid  = threadIdx.x;

    for (int i = tid; i < 16 * 64; i += 256) {
        int r = i >> 6, k = i & 63;
        int gr = row0 + r;
        float v = (gr < VOCAB && k < VEC_DIM) ? word_emb[gr * VEC_DIM + k] : 0.f;
        s_A[r * 66 + k] = __float2half_rn(v);
    }
    __syncthreads();

    int warp = tid >> 5, lane = tid & 31;
    int g = lane >> 2, t = lane & 3;

    unsigned uA[4][4];
    #pragma unroll
    for (int ks = 0; ks < 4; ks++) {
        int k0 = ks * 16;
        uA[ks][0] = *reinterpret_cast<unsigned*>(&s_A[ g      * 66 + k0 + 2*t    ]);
        uA[ks][1] = *reinterpret_cast<unsigned*>(&s_A[(g + 8) * 66 + k0 + 2*t    ]);
        uA[ks][2] = *reinterpret_cast<unsigned*>(&s_A[ g      * 66 + k0 + 2*t + 8]);
        uA[ks][3] = *reinterpret_cast<unsigned*>(&s_A[(g + 8) * 66 + k0 + 2*t + 8]);
    }

    for (int ct = warp; ct < NCOLT; ct += 8) {
        const uint2* bf = g_Bf + ct * 128 + lane;   // coalesced fragment loads
        float c0 = 0.f, c1 = 0.f, c2 = 0.f, c3 = 0.f;
        #pragma unroll
        for (int ks = 0; ks < 4; ks++) {
            uint2 b = bf[ks * 32];
            asm volatile(
                "mma.sync.aligned.m16n8k16.row.col.f32.f16.f16.f32 "
                "{%0,%1,%2,%3}, {%4,%5,%6,%7}, {%8,%9}, {%0,%1,%2,%3};"
                : "+f"(c0), "+f"(c1), "+f"(c2), "+f"(c3)
                : "r"(uA[ks][0]), "r"(uA[ks][1]), "r"(uA[ks][2]), "r"(uA[ks][3]),
                  "r"(b.x), "r"(b.y));
        }
        int col = ct * 8 + 2 * t;
        *reinterpret_cast<__half2*>(&s_D[ g      * SDSTR + col]) = __floats2half2_rn(c0, c1);
        *reinterpret_cast<__half2*>(&s_D[(g + 8) * SDSTR + col]) = __floats2half2_rn(c2, c3);
    }
    __syncthreads();

    // coalesced copy-out: 16 rows x 90 uint4 (16B) per row
    int nrow = VOCAB - row0;  if (nrow > 16) nrow = 16;
    for (int i = tid; i < nrow * 90; i += 256) {
        int r = i / 90, u = i - r * 90;
        uint4 val = *reinterpret_cast<uint4*>(&s_D[r * SDSTR + u * 8]);
        *reinterpret_cast<uint4*>(&g_Tw[(size_t)(row0 + r) * ROWW + u * 8]) = val;
    }
}

// ---------------- kernel 4: main fused conv-via-gather + maxpool + relu ----------------
// R6 champion structure: half2 math + full 9-load 1-deep register prefetch.
// block = 128 threads = 2 sentences x 64 lanes; lane tc<60 owns 4 channels.
__global__ __launch_bounds__(128, 8) void k_main(const int* __restrict__ X,
                                                 const int* __restrict__ P1,
                                                 const int* __restrict__ P2,
                                                 const float* __restrict__ conv_b) {
    __shared__ int   s_off[2][3][LSEQ + 1];   // precomputed BYTE offsets (+1 dummy token)
    __shared__ float s_b[PADC];
    int tid = threadIdx.x;
    int grp = tid >> 6, tc = tid & 63;
    int sent0 = blockIdx.x * 2;

    for (int i = tid; i < 2 * LSEQ; i += 128) {
        int g = i >> 7, t = i & (LSEQ - 1);
        int s = sent0 + g;
        s_off[g][0][t] = X [s * LSEQ + t] * ROWB;
        s_off[g][1][t] = P1[s * LSEQ + t] * ROWB;
        s_off[g][2][t] = P2[s * LSEQ + t] * ROWB;
    }
    if (tid < 2) {                          // dummy token for prefetch overrun
        s_off[tid][0][LSEQ] = 0;
        s_off[tid][1][LSEQ] = 0;
        s_off[tid][2][LSEQ] = 0;
    }
    for (int i = tid; i < PADC; i += 128) s_b[i] = (i < HID) ? conv_b[i] : 0.f;
    __syncthreads();

    if (tc >= 60) return;
    int cb = tc * 8;                        // channel byte offset within row

    const int* ow = s_off[grp][0];
    const int* o1 = s_off[grp][1];
    const int* o2 = s_off[grp][2];
    const char* baseW = (const char*)g_Tw  + cb;
    const char* base1 = (const char*)g_Tp1 + cb;
    const char* base2 = (const char*)g_Tp2 + cb;

    __half2 maxA  = __float2half2_rn(-60000.f), maxB = maxA;
    __half2 pendA = __float2half2_rn(-16384.f), pendB = pendA;  // absorbs t=0 max-update
    __half2 prevA = __float2half2_rn(0.f),      prevB = prevA;

    // prologue: load t=0
    const char* rw = baseW + ow[0];
    const char* r1 = base1 + o1[0];
    const char* r2 = base2 + o2[0];
    uint2 w0 = ldu2b(rw);  uint2 w1 = ldu2b(rw + 2*PADC);  uint2 w2 = ldu2b(rw + 4*PADC);
    uint2 q0 = ldu2b(r1);  uint2 q1 = ldu2b(r1 + 2*PADC);  uint2 q2 = ldu2b(r1 + 4*PADC);
    uint2 v0 = ldu2b(r2);  uint2 v1 = ldu2b(r2 + 2*PADC);  uint2 v2 = ldu2b(r2 + 4*PADC);

    #pragma unroll 4
    for (int t = 0; t < LSEQ; t++) {
        // issue ALL loads for t+1 before computing on t
        const char* nw = baseW + ow[t + 1];
        const char* n1 = base1 + o1[t + 1];
        const char* n2 = base2 + o2[t + 1];
        uint2 W0 = ldu2b(nw);  uint2 W1 = ldu2b(nw + 2*PADC);  uint2 W2 = ldu2b(nw + 4*PADC);
        uint2 Q0 = ldu2b(n1);  uint2 Q1 = ldu2b(n1 + 2*PADC);  uint2 Q2 = ldu2b(n1 + 4*PADC);
        uint2 V0 = ldu2b(n2);  uint2 V1 = ldu2b(n2 + 2*PADC);  uint2 V2 = ldu2b(n2 + 4*PADC);

        __half2 a2A = __hadd2(__hadd2(h2lo(w2), h2lo(q2)), h2lo(v2));
        __half2 a2B = __hadd2(__hadd2(h2hi(w2), h2hi(q2)), h2hi(v2));
        maxA = __hmax2(maxA, __hadd2(pendA, a2A));      // h[t-1]
        maxB = __hmax2(maxB, __hadd2(pendB, a2B));
        __half2 a1A = __hadd2(__hadd2(h2lo(w1), h2lo(q1)), h2lo(v1));
        __half2 a1B = __hadd2(__hadd2(h2hi(w1), h2hi(q1)), h2hi(v1));
        pendA = __hadd2(prevA, a1A);
        pendB = __hadd2(prevB, a1B);
        prevA = __hadd2(__hadd2(h2lo(w0), h2lo(q0)), h2lo(v0));
        prevB = __hadd2(__hadd2(h2hi(w0), h2hi(q0)), h2hi(v0));

        w0 = W0; w1 = W1; w2 = W2;
        q0 = Q0; q1 = Q1; q2 = Q2;
        v0 = V0; v1 = V1; v2 = V2;
    }
    maxA = __hmax2(maxA, pendA);            // h[L-1] (a2 of pad token = 0)
    maxB = __hmax2(maxB, pendB);

    float2 mA = __half22float2(maxA);
    float2 mB = __half22float2(maxB);
    int s = sent0 + grp;
    int coff = tc * 4;
    g_H[s * PADC + coff + 0] = fmaxf(mA.x + s_b[coff + 0], 0.f);
    g_H[s * PADC + coff + 1] = fmaxf(mA.y + s_b[coff + 1], 0.f);
    g_H[s * PADC + coff + 2] = fmaxf(mB.x + s_b[coff + 2], 0.f);
    g_H[s * PADC + coff + 3] = fmaxf(mB.y + s_b[coff + 3], 0.f);
}

// ---------------- kernel 5: per-bag softmax attention + classifier ----------------
__global__ __launch_bounds__(256) void k_bags(const int* __restrict__ scope,
                                              const int* __restrict__ relation,
                                              const float* __restrict__ rel_w,
                                              const float* __restrict__ rel_b,
                                              float* __restrict__ out) {
    int b = blockIdx.x;
    __shared__ float s_q[HID];
    __shared__ float s_logit[8];
    __shared__ float s_alpha[8];
    __shared__ float s_rep[HID];

    int tid = threadIdx.x;
    int w = tid >> 5, lane = tid & 31;
    int s0 = scope[2 * b], s1 = scope[2 * b + 1];
    int sz = s1 - s0;
    if (sz > 8) sz = 8;
    int rq = relation[b];

    for (int c = tid; c < HID; c += 256) s_q[c] = rel_w[rq * HID + c];
    __syncthreads();

    if (w < 8) {
        float acc = 0.f;
        if (w < sz) {
            const float* hp = g_H + (size_t)(s0 + w) * PADC;
            for (int c = lane; c < HID; c += 32) acc = fmaf(hp[c], s_q[c], acc);
        }
        #pragma unroll
        for (int o = 16; o; o >>= 1) acc += __shfl_xor_sync(0xffffffffu, acc, o);
        if (lane == 0) s_logit[w] = (w < sz) ? acc : -1e30f;
    }
    __syncthreads();

    if (tid == 0) {
        float m = -1e30f;
        for (int i = 0; i < sz; i++) m = fmaxf(m, s_logit[i]);
        float d = 0.f;
        for (int i = 0; i < sz; i++) { float e = expf(s_logit[i] - m); s_alpha[i] = e; d += e; }
        float inv = 1.f / d;
        for (int i = 0; i < sz; i++) s_alpha[i] *= inv;
    }
    __syncthreads();

    for (int c = tid; c < HID; c += 256) {
        float acc = 0.f;
        for (int i = 0; i < sz; i++)
            acc = fmaf(s_alpha[i], g_H[(size_t)(s0 + i) * PADC + c], acc);
        s_rep[c] = acc;
    }
    __syncthreads();

    for (int rr = w; rr < NREL; rr += 8) {
        float acc = 0.f;
        for (int c = lane; c < HID; c += 32) acc = fmaf(s_rep[c], rel_w[rr * HID + c], acc);
        #pragma unroll
        for (int o = 16; o; o >>= 1) acc += __shfl_xor_sync(0xffffffffu, acc, o);
        if (lane == 0) out[b * NREL + rr] = acc + rel_b[rr];
    }
}

// ---------------- launch ----------------
extern "C" void kernel_launch(void* const* d_in, const int* in_sizes, int n_in,
                              void* d_out, int out_size) {
    const int*   X        = (const int*)  d_in[0];
    const int*   P1       = (const int*)  d_in[1];
    const int*   P2       = (const int*)  d_in[2];
    // d_in[3] mask, d_in[4] length: unused
    const int*   scope    = (const int*)  d_in[5];
    const int*   relation = (const int*)  d_in[6];
    const float* word_emb = (const float*)d_in[7];
    const float* p1e      = (const float*)d_in[8];
    const float* p2e      = (const float*)d_in[9];
    const float* conv_w   = (const float*)d_in[10];
    const float* conv_b   = (const float*)d_in[11];
    const float* rel_w    = (const float*)d_in[12];
    const float* rel_b    = (const float*)d_in[13];
    float* out = (float*)d_out;

    k_prep_Bf<<<(NCOLT * 4 * 32 + 255) / 256, 256>>>(conv_w);
    k_pos_tables<<<NPOS, ROWW>>>(p1e, p2e, conv_w);
    k_build_word<<<NROWT, 256>>>(word_emb);
    k_main<<<NSENT / 2, 128>>>(X, P1, P2, conv_b);
    k_bags<<<NBAG, 256>>>(scope, relation, rel_w, rel_b, out);
}

// round 16
// speedup vs baseline: 2.7948x; 1.0661x over previous
#include <cuda_runtime.h>
#include <cuda_fp16.h>

// ---------------- problem constants ----------------
#define NSENT   4000
#define LSEQ    128
#define VOCAB   50002
#define VEC_DIM 50
#define POS_DIM 5
#define EMB     60
#define HID     230
#define PADC    240            // HID padded to 240
#define ROWW    (3*PADC)       // 720 entries per table row (3 kernel taps)
#define ROWB    (ROWW*2)       // row stride in bytes (fp16)
#define NCOLT   (ROWW/8)       // 90 col-tiles of 8
#define MROWS   32             // vocab rows per build block
#define NROWT   ((VOCAB+MROWS-1)/MROWS)   // 1563
#define SDSTR   728            // s_D row stride in halfs (16B-aligned, conflict-free)
#define NPOS    201
#define NBAG    500
#define NREL    25

#define BUILD_SMEM ((MROWS*66 + MROWS*SDSTR) * 2)   // 50816 B dynamic

// ---------------- device scratch (static; no runtime allocation) ----------------
__device__ uint2  g_Bf [NCOLT * 4 * 32];            // B in MMA-fragment order (90 KB)
__device__ __half g_Tw [(size_t)VOCAB * ROWW];      // word projection table (fp16, ~72 MB)
__device__ __half g_Tp1[NPOS * ROWW];               // pos1 projection table (fp16, 289 KB)
__device__ __half g_Tp2[NPOS * ROWW];               // pos2 projection table (fp16, 289 KB)
__device__ float  g_H  [NSENT * PADC];              // sentence encodings

// ---------------- helpers ----------------
__device__ __forceinline__ uint2 ldu2b(const char* p) {
    return *reinterpret_cast<const uint2*>(p);
}
__device__ __forceinline__ __half2 h2lo(uint2 u) { return *reinterpret_cast<__half2*>(&u.x); }
__device__ __forceinline__ __half2 h2hi(uint2 u) { return *reinterpret_cast<__half2*>(&u.y); }

// ---------------- kernel 1: merged prep (pos tables + B fragments) ----------------
// blocks 0..200: pos tables (thread r of 720). blocks 201..216: g_Bf entries.
__global__ __launch_bounds__(720) void k_prep(const float* __restrict__ p1e,
                                              const float* __restrict__ p2e,
                                              const float* __restrict__ conv_w) {
    if (blockIdx.x < NPOS) {
        int p = blockIdx.x;
        int r = threadIdx.x;           // 0..719
        int k = r / PADC;
        int c = r - k * PADC;
        float a1 = 0.f, a2 = 0.f;
        if (c < HID) {
            #pragma unroll
            for (int e = 0; e < POS_DIM; e++) {
                float w1 = conv_w[(c * EMB + VEC_DIM + e) * 3 + k];
                float w2 = conv_w[(c * EMB + VEC_DIM + POS_DIM + e) * 3 + k];
                a1 = fmaf(p1e[p * POS_DIM + e], w1, a1);
                a2 = fmaf(p2e[p * POS_DIM + e], w2, a2);
            }
        }
        g_Tp1[p * ROWW + r] = __float2half_rn(a1);
        g_Tp2[p * ROWW + r] = __float2half_rn(a2);
    } else {
        int i = (blockIdx.x - NPOS) * 720 + threadIdx.x;
        if (i >= NCOLT * 4 * 32) return;
        int lane = i & 31;
        int ks = (i >> 5) & 3;
        int ct = i >> 7;
        int g = lane >> 2, t = lane & 3;
        int n = ct * 8 + g;
        int tap = n / PADC, c = n - tap * PADC;
        int e0 = ks * 16 + 2 * t;
        float v0 = 0.f, v1 = 0.f, v2 = 0.f, v3 = 0.f;
        if (c < HID) {
            if (e0     < VEC_DIM) v0 = conv_w[(c * EMB + e0    ) * 3 + tap];
            if (e0 + 1 < VEC_DIM) v1 = conv_w[(c * EMB + e0 + 1) * 3 + tap];
            if (e0 + 8 < VEC_DIM) v2 = conv_w[(c * EMB + e0 + 8) * 3 + tap];
            if (e0 + 9 < VEC_DIM) v3 = conv_w[(c * EMB + e0 + 9) * 3 + tap];
        }
        __half2 x = __floats2half2_rn(v0, v1);
        __half2 y = __floats2half2_rn(v2, v3);
        uint2 st;
        st.x = *reinterpret_cast<unsigned*>(&x);
        st.y = *reinterpret_cast<unsigned*>(&y);
        g_Bf[i] = st;
    }
}

// ---------------- kernel 2: word table build, M=32/block, B-frag reuse x2 ----------------
__global__ __launch_bounds__(256) void k_build_word(const float* __restrict__ word_emb) {
    extern __shared__ __align__(16) __half smb[];
    __half* s_A = smb;                    // 32 x 66
    __half* s_D = smb + MROWS * 66;       // 32 x 728 (offset 4224 B, 16B-aligned)
    int row0 = blockIdx.x * MROWS;
    int tid  = threadIdx.x;

    for (int i = tid; i < MROWS * 64; i += 256) {
        int r = i >> 6, k = i & 63;
        int gr = row0 + r;
        float v = (gr < VOCAB && k < VEC_DIM) ? word_emb[gr * VEC_DIM + k] : 0.f;
        s_A[r * 66 + k] = __float2half_rn(v);
    }
    __syncthreads();

    int warp = tid >> 5, lane = tid & 31;
    int g = lane >> 2, t = lane & 3;

    // A fragments for 2 M-tiles x 4 k-steps
    unsigned uA[2][4][4];
    #pragma unroll
    for (int mt = 0; mt < 2; mt++) {
        int rb = mt * 16;
        #pragma unroll
        for (int ks = 0; ks < 4; ks++) {
            int k0 = ks * 16;
            uA[mt][ks][0] = *reinterpret_cast<unsigned*>(&s_A[(rb + g    ) * 66 + k0 + 2*t    ]);
            uA[mt][ks][1] = *reinterpret_cast<unsigned*>(&s_A[(rb + g + 8) * 66 + k0 + 2*t    ]);
            uA[mt][ks][2] = *reinterpret_cast<unsigned*>(&s_A[(rb + g    ) * 66 + k0 + 2*t + 8]);
            uA[mt][ks][3] = *reinterpret_cast<unsigned*>(&s_A[(rb + g + 8) * 66 + k0 + 2*t + 8]);
        }
    }

    for (int ct = warp; ct < NCOLT; ct += 8) {
        const uint2* bf = g_Bf + ct * 128 + lane;   // coalesced fragment loads
        float c00=0.f,c01=0.f,c02=0.f,c03=0.f;      // M-tile 0
        float c10=0.f,c11=0.f,c12=0.f,c13=0.f;      // M-tile 1
        #pragma unroll
        for (int ks = 0; ks < 4; ks++) {
            uint2 b = bf[ks * 32];                   // one load feeds BOTH tiles
            asm volatile(
                "mma.sync.aligned.m16n8k16.row.col.f32.f16.f16.f32 "
                "{%0,%1,%2,%3}, {%4,%5,%6,%7}, {%8,%9}, {%0,%1,%2,%3};"
                : "+f"(c00), "+f"(c01), "+f"(c02), "+f"(c03)
                : "r"(uA[0][ks][0]), "r"(uA[0][ks][1]), "r"(uA[0][ks][2]), "r"(uA[0][ks][3]),
                  "r"(b.x), "r"(b.y));
            asm volatile(
                "mma.sync.aligned.m16n8k16.row.col.f32.f16.f16.f32 "
                "{%0,%1,%2,%3}, {%4,%5,%6,%7}, {%8,%9}, {%0,%1,%2,%3};"
                : "+f"(c10), "+f"(c11), "+f"(c12), "+f"(c13)
                : "r"(uA[1][ks][0]), "r"(uA[1][ks][1]), "r"(uA[1][ks][2]), "r"(uA[1][ks][3]),
                  "r"(b.x), "r"(b.y));
        }
        int col = ct * 8 + 2 * t;
        *reinterpret_cast<__half2*>(&s_D[( g     ) * SDSTR + col]) = __floats2half2_rn(c00, c01);
        *reinterpret_cast<__half2*>(&s_D[( g + 8 ) * SDSTR + col]) = __floats2half2_rn(c02, c03);
        *reinterpret_cast<__half2*>(&s_D[(16 + g    ) * SDSTR + col]) = __floats2half2_rn(c10, c11);
        *reinterpret_cast<__half2*>(&s_D[(16 + g + 8) * SDSTR + col]) = __floats2half2_rn(c12, c13);
    }
    __syncthreads();

    // coalesced copy-out: nrow rows x 90 uint4 (16B) per row
    int nrow = VOCAB - row0;  if (nrow > MROWS) nrow = MROWS;
    for (int i = tid; i < nrow * 90; i += 256) {
        int r = i / 90, u = i - r * 90;
        uint4 val = *reinterpret_cast<uint4*>(&s_D[r * SDSTR + u * 8]);
        *reinterpret_cast<uint4*>(&g_Tw[(size_t)(row0 + r) * ROWW + u * 8]) = val;
    }
}

// ---------------- kernel 3: main fused conv-via-gather + maxpool + relu ----------------
// R6 champion structure: half2 math + full 9-load 1-deep register prefetch.
__global__ __launch_bounds__(128, 8) void k_main(const int* __restrict__ X,
                                                 const int* __restrict__ P1,
                                                 const int* __restrict__ P2,
                                                 const float* __restrict__ conv_b) {
    __shared__ int   s_off[2][3][LSEQ + 1];   // precomputed BYTE offsets (+1 dummy token)
    __shared__ float s_b[PADC];
    int tid = threadIdx.x;
    int grp = tid >> 6, tc = tid & 63;
    int sent0 = blockIdx.x * 2;

    for (int i = tid; i < 2 * LSEQ; i += 128) {
        int g = i >> 7, t = i & (LSEQ - 1);
        int s = sent0 + g;
        s_off[g][0][t] = X [s * LSEQ + t] * ROWB;
        s_off[g][1][t] = P1[s * LSEQ + t] * ROWB;
        s_off[g][2][t] = P2[s * LSEQ + t] * ROWB;
    }
    if (tid < 2) {                          // dummy token for prefetch overrun
        s_off[tid][0][LSEQ] = 0;
        s_off[tid][1][LSEQ] = 0;
        s_off[tid][2][LSEQ] = 0;
    }
    for (int i = tid; i < PADC; i += 128) s_b[i] = (i < HID) ? conv_b[i] : 0.f;
    __syncthreads();

    if (tc >= 60) return;
    int cb = tc * 8;                        // channel byte offset within row

    const int* ow = s_off[grp][0];
    const int* o1 = s_off[grp][1];
    const int* o2 = s_off[grp][2];
    const char* baseW = (const char*)g_Tw  + cb;
    const char* base1 = (const char*)g_Tp1 + cb;
    const char* base2 = (const char*)g_Tp2 + cb;

    __half2 maxA  = __float2half2_rn(-60000.f), maxB = maxA;
    __half2 pendA = __float2half2_rn(-16384.f), pendB = pendA;  // absorbs t=0 max-update
    __half2 prevA = __float2half2_rn(0.f),      prevB = prevA;

    // prologue: load t=0
    const char* rw = baseW + ow[0];
    const char* r1 = base1 + o1[0];
    const char* r2 = base2 + o2[0];
    uint2 w0 = ldu2b(rw);  uint2 w1 = ldu2b(rw + 2*PADC);  uint2 w2 = ldu2b(rw + 4*PADC);
    uint2 q0 = ldu2b(r1);  uint2 q1 = ldu2b(r1 + 2*PADC);  uint2 q2 = ldu2b(r1 + 4*PADC);
    uint2 v0 = ldu2b(r2);  uint2 v1 = ldu2b(r2 + 2*PADC);  uint2 v2 = ldu2b(r2 + 4*PADC);

    #pragma unroll 4
    for (int t = 0; t < LSEQ; t++) {
        // issue ALL loads for t+1 before computing on t
        const char* nw = baseW + ow[t + 1];
        const char* n1 = base1 + o1[t + 1];
        const char* n2 = base2 + o2[t + 1];
        uint2 W0 = ldu2b(nw);  uint2 W1 = ldu2b(nw + 2*PADC);  uint2 W2 = ldu2b(nw + 4*PADC);
        uint2 Q0 = ldu2b(n1);  uint2 Q1 = ldu2b(n1 + 2*PADC);  uint2 Q2 = ldu2b(n1 + 4*PADC);
        uint2 V0 = ldu2b(n2);  uint2 V1 = ldu2b(n2 + 2*PADC);  uint2 V2 = ldu2b(n2 + 4*PADC);

        __half2 a2A = __hadd2(__hadd2(h2lo(w2), h2lo(q2)), h2lo(v2));
        __half2 a2B = __hadd2(__hadd2(h2hi(w2), h2hi(q2)), h2hi(v2));
        maxA = __hmax2(maxA, __hadd2(pendA, a2A));      // h[t-1]
        maxB = __hmax2(maxB, __hadd2(pendB, a2B));
        __half2 a1A = __hadd2(__hadd2(h2lo(w1), h2lo(q1)), h2lo(v1));
        __half2 a1B = __hadd2(__hadd2(h2hi(w1), h2hi(q1)), h2hi(v1));
        pendA = __hadd2(prevA, a1A);
        pendB = __hadd2(prevB, a1B);
        prevA = __hadd2(__hadd2(h2lo(w0), h2lo(q0)), h2lo(v0));
        prevB = __hadd2(__hadd2(h2hi(w0), h2hi(q0)), h2hi(v0));

        w0 = W0; w1 = W1; w2 = W2;
        q0 = Q0; q1 = Q1; q2 = Q2;
        v0 = V0; v1 = V1; v2 = V2;
    }
    maxA = __hmax2(maxA, pendA);            // h[L-1] (a2 of pad token = 0)
    maxB = __hmax2(maxB, pendB);

    float2 mA = __half22float2(maxA);
    float2 mB = __half22float2(maxB);
    int s = sent0 + grp;
    int coff = tc * 4;
    g_H[s * PADC + coff + 0] = fmaxf(mA.x + s_b[coff + 0], 0.f);
    g_H[s * PADC + coff + 1] = fmaxf(mA.y + s_b[coff + 1], 0.f);
    g_H[s * PADC + coff + 2] = fmaxf(mB.x + s_b[coff + 2], 0.f);
    g_H[s * PADC + coff + 3] = fmaxf(mB.y + s_b[coff + 3], 0.f);
}

// ---------------- kernel 4: per-bag softmax attention + classifier ----------------
__global__ __launch_bounds__(256) void k_bags(const int* __restrict__ scope,
                                              const int* __restrict__ relation,
                                              const float* __restrict__ rel_w,
                                              const float* __restrict__ rel_b,
                                              float* __restrict__ out) {
    int b = blockIdx.x;
    __shared__ float s_q[HID];
    __shared__ float s_logit[8];
    __shared__ float s_alpha[8];
    __shared__ float s_rep[HID];

    int tid = threadIdx.x;
    int w = tid >> 5, lane = tid & 31;
    int s0 = scope[2 * b], s1 = scope[2 * b + 1];
    int sz = s1 - s0;
    if (sz > 8) sz = 8;
    int rq = relation[b];

    for (int c = tid; c < HID; c += 256) s_q[c] = rel_w[rq * HID + c];
    __syncthreads();

    if (w < 8) {
        float acc = 0.f;
        if (w < sz) {
            const float* hp = g_H + (size_t)(s0 + w) * PADC;
            for (int c = lane; c < HID; c += 32) acc = fmaf(hp[c], s_q[c], acc);
        }
        #pragma unroll
        for (int o = 16; o; o >>= 1) acc += __shfl_xor_sync(0xffffffffu, acc, o);
        if (lane == 0) s_logit[w] = (w < sz) ? acc : -1e30f;
    }
    __syncthreads();

    if (tid == 0) {
        float m = -1e30f;
        for (int i = 0; i < sz; i++) m = fmaxf(m, s_logit[i]);
        float d = 0.f;
        for (int i = 0; i < sz; i++) { float e = expf(s_logit[i] - m); s_alpha[i] = e; d += e; }
        float inv = 1.f / d;
        for (int i = 0; i < sz; i++) s_alpha[i] *= inv;
    }
    __syncthreads();

    for (int c = tid; c < HID; c += 256) {
        float acc = 0.f;
        for (int i = 0; i < sz; i++)
            acc = fmaf(s_alpha[i], g_H[(size_t)(s0 + i) * PADC + c], acc);
        s_rep[c] = acc;
    }
    __syncthreads();

    for (int rr = w; rr < NREL; rr += 8) {
        float acc = 0.f;
        for (int c = lane; c < HID; c += 32) acc = fmaf(s_rep[c], rel_w[rr * HID + c], acc);
        #pragma unroll
        for (int o = 16; o; o >>= 1) acc += __shfl_xor_sync(0xffffffffu, acc, o);
        if (lane == 0) out[b * NREL + rr] = acc + rel_b[rr];
    }
}

// ---------------- launch ----------------
extern "C" void kernel_launch(void* const* d_in, const int* in_sizes, int n_in,
                              void* d_out, int out_size) {
    const int*   X        = (const int*)  d_in[0];
    const int*   P1       = (const int*)  d_in[1];
    const int*   P2       = (const int*)  d_in[2];
    // d_in[3] mask, d_in[4] length: unused
    const int*   scope    = (const int*)  d_in[5];
    const int*   relation = (const int*)  d_in[6];
    const float* word_emb = (const float*)d_in[7];
    const float* p1e      = (const float*)d_in[8];
    const float* p2e      = (const float*)d_in[9];
    const float* conv_w   = (const float*)d_in[10];
    const float* conv_b   = (const float*)d_in[11];
    const float* rel_w    = (const float*)d_in[12];
    const float* rel_b    = (const float*)d_in[13];
    float* out = (float*)d_out;

    cudaFuncSetAttribute(k_build_word, cudaFuncAttributeMaxDynamicSharedMemorySize, BUILD_SMEM);

    // 201 pos blocks + 16 Bf blocks (16*720 = 11520 = NCOLT*4*32)
    k_prep<<<NPOS + 16, 720>>>(p1e, p2e, conv_w);
    k_build_word<<<NROWT, 256, BUILD_SMEM>>>(word_emb);
    k_main<<<NSENT / 2, 128>>>(X, P1, P2, conv_b);
    k_bags<<<NBAG, 256>>>(scope, relation, rel_w, rel_b, out);
}